// round 4
// baseline (speedup 1.0000x reference)
#include <cuda_runtime.h>
#include <math.h>

// Problem constants
#define B      1024
#define D      512
#define C      100000
#define TILE   128
#define KC     16
#define NT     ((C + TILE - 1) / TILE)   // 782 class tiles
#define SCALE_F 64.0f

// ArcFace margin constants (margin = 0.5)
#define COS_M  0.8775825618903728f
#define SIN_M  0.47942553860420301f
#define TH_M  (-0.8775825618903728f)
#define MM_M   0.23971276930210151f

// Scratch (no allocations allowed -> __device__ globals)
__device__ float g_einv[B];
__device__ float g_winv[C];
__device__ float g_ldot[B];
__device__ float g_pmax[NT * B];
__device__ float g_psum[NT * B];

// ---------------------------------------------------------------------------
// Inverse L2 norms of embedding rows (1024 x 512). One warp per row.
// ---------------------------------------------------------------------------
__global__ void e_norm_kernel(const float* __restrict__ E) {
    int warp = (blockIdx.x * blockDim.x + threadIdx.x) >> 5;
    int lane = threadIdx.x & 31;
    if (warp >= B) return;
    const float* row = E + (size_t)warp * D;
    float ss = 0.f;
    #pragma unroll
    for (int i = 0; i < D / 32; i++) {
        float v = row[lane + i * 32];
        ss = fmaf(v, v, ss);
    }
    #pragma unroll
    for (int o = 16; o > 0; o >>= 1) ss += __shfl_xor_sync(0xffffffffu, ss, o);
    if (lane == 0) g_einv[warp] = 1.0f / fmaxf(sqrtf(ss), 1e-12f);
}

// ---------------------------------------------------------------------------
// Inverse L2 norms of weight rows (100000 x 512). One warp per row.
// ---------------------------------------------------------------------------
__global__ void w_norm_kernel(const float* __restrict__ W) {
    int warp = (blockIdx.x * blockDim.x + threadIdx.x) >> 5;
    int lane = threadIdx.x & 31;
    if (warp >= C) return;
    const float* row = W + (size_t)warp * D;
    float ss = 0.f;
    #pragma unroll
    for (int i = 0; i < D / 32; i++) {
        float v = row[lane + i * 32];
        ss = fmaf(v, v, ss);
    }
    #pragma unroll
    for (int o = 16; o > 0; o >>= 1) ss += __shfl_xor_sync(0xffffffffu, ss, o);
    if (lane == 0) g_winv[warp] = 1.0f / fmaxf(sqrtf(ss), 1e-12f);
}

// ---------------------------------------------------------------------------
// Raw dot(e_b, w_label[b]) for each row. One warp per row.
// NOTE: labels are int32 (harness contract), not int64.
// ---------------------------------------------------------------------------
__global__ void label_dot_kernel(const float* __restrict__ E,
                                 const float* __restrict__ W,
                                 const int* __restrict__ labels) {
    int warp = (blockIdx.x * blockDim.x + threadIdx.x) >> 5;
    int lane = threadIdx.x & 31;
    if (warp >= B) return;
    int lab = labels[warp];
    const float* e = E + (size_t)warp * D;
    const float* w = W + (size_t)lab * D;
    float s = 0.f;
    #pragma unroll
    for (int i = 0; i < D / 32; i++) {
        s = fmaf(e[lane + i * 32], w[lane + i * 32], s);
    }
    #pragma unroll
    for (int o = 16; o > 0; o >>= 1) s += __shfl_xor_sync(0xffffffffu, s, o);
    if (lane == 0) g_ldot[warp] = s;
}

// ---------------------------------------------------------------------------
// Main: 128x128 tile GEMM (raw dot products) + fused per-tile online-softmax
// partials. grid = (8 row tiles, 782 class tiles); blocks with the same class
// tile are adjacent in launch order so the weight tile is read from HBM once
// and hit in L2 by the other 7 row tiles.
// ---------------------------------------------------------------------------
__global__ void __launch_bounds__(256)
gemm_softmax_kernel(const float* __restrict__ E, const float* __restrict__ W) {
    const int rowTile   = blockIdx.x;      // 0..7
    const int classTile = blockIdx.y;      // 0..NT-1
    const int rowBase   = rowTile * TILE;
    const int classBase = classTile * TILE;

    __shared__ float As[KC][TILE];
    __shared__ float Bs[KC][TILE];

    const int t  = threadIdx.x;
    const int tx = t & 15;     // class sub-tile
    const int ty = t >> 4;     // row sub-tile

    float acc[8][8];
    #pragma unroll
    for (int i = 0; i < 8; i++)
        #pragma unroll
        for (int j = 0; j < 8; j++) acc[i][j] = 0.f;

    // Loader mapping: thread loads 8 consecutive k-floats of one tile row.
    const int lr = t >> 1;            // tile row 0..127
    const int lk = (t & 1) * 8;       // k offset 0 or 8

    const float* Eg = E + (size_t)(rowBase + lr) * D + lk;
    const int    wc = classBase + lr;
    const bool   wvalid = (wc < C);
    const float* Wg = W + (size_t)(wvalid ? wc : 0) * D + lk;

    for (int k0 = 0; k0 < D; k0 += KC) {
        float4 a0 = *(const float4*)(Eg + k0);
        float4 a1 = *(const float4*)(Eg + k0 + 4);
        float4 b0 = make_float4(0.f, 0.f, 0.f, 0.f);
        float4 b1 = make_float4(0.f, 0.f, 0.f, 0.f);
        if (wvalid) {
            b0 = *(const float4*)(Wg + k0);
            b1 = *(const float4*)(Wg + k0 + 4);
        }
        __syncthreads();   // previous compute finished reading smem
        As[lk + 0][lr] = a0.x; As[lk + 1][lr] = a0.y;
        As[lk + 2][lr] = a0.z; As[lk + 3][lr] = a0.w;
        As[lk + 4][lr] = a1.x; As[lk + 5][lr] = a1.y;
        As[lk + 6][lr] = a1.z; As[lk + 7][lr] = a1.w;
        Bs[lk + 0][lr] = b0.x; Bs[lk + 1][lr] = b0.y;
        Bs[lk + 2][lr] = b0.z; Bs[lk + 3][lr] = b0.w;
        Bs[lk + 4][lr] = b1.x; Bs[lk + 5][lr] = b1.y;
        Bs[lk + 6][lr] = b1.z; Bs[lk + 7][lr] = b1.w;
        __syncthreads();

        #pragma unroll
        for (int kk = 0; kk < KC; kk++) {
            float4 av0 = *(const float4*)&As[kk][ty * 8];
            float4 av1 = *(const float4*)&As[kk][ty * 8 + 4];
            float4 bv0 = *(const float4*)&Bs[kk][tx * 8];
            float4 bv1 = *(const float4*)&Bs[kk][tx * 8 + 4];
            float a[8] = {av0.x, av0.y, av0.z, av0.w, av1.x, av1.y, av1.z, av1.w};
            float b[8] = {bv0.x, bv0.y, bv0.z, bv0.w, bv1.x, bv1.y, bv1.z, bv1.w};
            #pragma unroll
            for (int i = 0; i < 8; i++)
                #pragma unroll
                for (int j = 0; j < 8; j++)
                    acc[i][j] = fmaf(a[i], b[j], acc[i][j]);
        }
    }

    // Epilogue: cosine -> logits -> per-tile per-row (max, sumexp)
    float einv_r[8], winv_c[8];
    bool  val[8];
    #pragma unroll
    for (int i = 0; i < 8; i++) einv_r[i] = g_einv[rowBase + ty * 8 + i];
    #pragma unroll
    for (int j = 0; j < 8; j++) {
        int c = classBase + tx * 8 + j;
        val[j]    = (c < C);
        winv_c[j] = val[j] ? g_winv[c] : 0.f;
    }

    #pragma unroll
    for (int i = 0; i < 8; i++) {
        float lg[8];
        float m = -INFINITY;
        #pragma unroll
        for (int j = 0; j < 8; j++) {
            lg[j] = val[j] ? (SCALE_F * acc[i][j] * einv_r[i] * winv_c[j])
                           : -INFINITY;
            m = fmaxf(m, lg[j]);
        }
        // reduce across the 16 tx-threads (contiguous 16-lane group)
        #pragma unroll
        for (int o = 1; o < 16; o <<= 1)
            m = fmaxf(m, __shfl_xor_sync(0xffffffffu, m, o));
        float s = 0.f;
        #pragma unroll
        for (int j = 0; j < 8; j++) s += expf(lg[j] - m);   // exp(-inf)=0 for oob
        #pragma unroll
        for (int o = 1; o < 16; o <<= 1)
            s += __shfl_xor_sync(0xffffffffu, s, o);
        if (tx == 0) {
            int b = rowBase + ty * 8 + i;
            g_pmax[classTile * B + b] = m;
            g_psum[classTile * B + b] = s;
        }
    }
}

// ---------------------------------------------------------------------------
// Finalize: merge NT partials per row, apply margin correction at the label,
// compute NLL, block-reduce mean. One block of 1024 threads (thread = row).
// NOTE: labels are int32 (harness contract), not int64.
// ---------------------------------------------------------------------------
__global__ void finalize_kernel(const int* __restrict__ labels,
                                float* __restrict__ out) {
    const int b = threadIdx.x;
    float m = -INFINITY, s = 0.f;
    for (int t2 = 0; t2 < NT; t2++) {
        float mt = g_pmax[t2 * B + b];
        float st = g_psum[t2 * B + b];
        if (mt > m) { s = s * expf(m - mt) + st; m = mt; }
        else        { s += st * expf(mt - m); }
    }

    int lab = labels[b];
    float cosl = g_ldot[b] * g_einv[b] * g_winv[lab];
    float c2   = 1.0f - cosl * cosl;
    float sine = sqrtf(fminf(fmaxf(c2, 0.f), 1.f));
    float phi  = cosl * COS_M - sine * SIN_M;
    phi = (cosl > TH_M) ? phi : (cosl - MM_M);

    float lo = SCALE_F * cosl;    // original logit at the label
    float ln = SCALE_F * phi;     // margined logit (ln <= lo <= m always)
    s += expf(ln - m) - expf(lo - m);

    float nll = m + logf(s) - ln;

    __shared__ float red[B];
    red[b] = nll;
    __syncthreads();
    #pragma unroll
    for (int o = B / 2; o > 0; o >>= 1) {
        if (b < o) red[b] += red[b + o];
        __syncthreads();
    }
    if (b == 0) out[0] = red[0] / (float)B;
}

// ---------------------------------------------------------------------------
extern "C" void kernel_launch(void* const* d_in, const int* in_sizes, int n_in,
                              void* d_out, int out_size) {
    const float* E      = (const float*)d_in[0];
    const float* W      = (const float*)d_in[1];
    const int*   labels = (const int*)d_in[2];
    float*       out    = (float*)d_out;

    e_norm_kernel<<<(B * 32) / 256, 256>>>(E);
    w_norm_kernel<<<(C * 32 + 255) / 256, 256>>>(W);
    label_dot_kernel<<<(B * 32) / 256, 256>>>(E, W, labels);

    dim3 grid(B / TILE, NT);   // (8, 782); x-major order => weight-tile L2 reuse
    gemm_softmax_kernel<<<grid, 256>>>(E, W);

    finalize_kernel<<<1, B>>>(labels, out);
}